// round 11
// baseline (speedup 1.0000x reference)
#include <cuda_runtime.h>
#include <cuda_fp16.h>
#include <math.h>

// Sinkhorn on GB300 — persistent kernel, 512 thr/block, prefetched E loads.
//   Eh = exp(-C/eps) in fp16 (64 MB, L2-resident).
//   Lane owns 32 fixed columns (16 f32x2). Per row: unpack current raw int4s,
//   IMMEDIATELY issue next row's 4 LDG.128 (loads overlap the dot/exchange/
//   acc chain -> continuous L2 issue), then dot + pair-exchange + acc.
//   Register budget ~124/thread at 512 thr (raw16+ef32+wv32+acc32+misc).

#define P 2048
#define NB 8
#define INV_EPS 10.0f
#define LOG_EPS 1e-8f
#define MAX_ITER 50
#define TOT 33554432           // NB * P * P
#define NBLK 128               // 8 batches x 16 row-blocks; co-resident

typedef unsigned long long ull;

__device__ __half g_Eh[TOT];
__device__ float g_wu[NB * P];
__device__ float g_wv[NB * P];
__device__ float g_bpart[NB * 16 * P];   // 1 MB block partials
__device__ float g_costpart[NB * P];

__device__ unsigned g_arrive;            // zero-init
__device__ volatile unsigned g_gen;

__device__ __forceinline__ float2 h2f(unsigned int u) {
    __half2 h = *reinterpret_cast<__half2*>(&u);
    return __half22float2(h);
}
__device__ __forceinline__ ull pk(float a, float b) {
    ull r; asm("mov.b64 %0, {%1, %2};" : "=l"(r) : "f"(a), "f"(b)); return r;
}
__device__ __forceinline__ void upk(float& a, float& b, ull r) {
    asm("mov.b64 {%0, %1}, %2;" : "=f"(a), "=f"(b) : "l"(r));
}
__device__ __forceinline__ ull ffma2(ull a, ull b, ull c) {
    ull d; asm("fma.rn.f32x2 %0, %1, %2, %3;" : "=l"(d) : "l"(a), "l"(b), "l"(c));
    return d;
}

// sense-reversing grid barrier; all NBLK blocks co-resident (1 block/SM).
__device__ __forceinline__ void grid_sync() {
    __syncthreads();
    if (threadIdx.x == 0) {
        unsigned g = g_gen;
        __threadfence();
        if (atomicAdd(&g_arrive, 1u) == NBLK - 1) {
            g_arrive = 0;
            __threadfence();
            g_gen = g + 1;
        } else {
            while (g_gen == g) __nanosleep(64);
        }
        __threadfence();
    }
    __syncthreads();
}

// ---------------------------------------------------------------- precompute
__global__ void precompute_E(const float* __restrict__ C) {
    size_t stride = (size_t)gridDim.x * blockDim.x;
    const float4* c4 = (const float4*)C;
    int4* e4 = (int4*)g_Eh;
    for (size_t k = (size_t)blockIdx.x * blockDim.x + threadIdx.x;
         k < (size_t)TOT / 8; k += stride) {
        float4 a = c4[2 * k], b = c4[2 * k + 1];
        __half2 h0 = __floats2half2_rn(expf(-a.x * INV_EPS), expf(-a.y * INV_EPS));
        __half2 h1 = __floats2half2_rn(expf(-a.z * INV_EPS), expf(-a.w * INV_EPS));
        __half2 h2 = __floats2half2_rn(expf(-b.x * INV_EPS), expf(-b.y * INV_EPS));
        __half2 h3 = __floats2half2_rn(expf(-b.z * INV_EPS), expf(-b.w * INV_EPS));
        int4 o;
        o.x = *reinterpret_cast<int*>(&h0);
        o.y = *reinterpret_cast<int*>(&h1);
        o.z = *reinterpret_cast<int*>(&h2);
        o.w = *reinterpret_cast<int*>(&h3);
        e4[k] = o;
    }
}

// --------------------------------------------------------- persistent kernel
// block = (n, rblk): rows [rblk*128, +128). 16 warps: h = wid>>3 (col half),
// p = wid&7 (rows p*16..p*16+15). lane owns cols h*1024+256c+8*lane+h2.
__global__ void __launch_bounds__(512, 1)
sinkhorn_persist(const float* __restrict__ mu, const float* __restrict__ nu) {
    int n = blockIdx.x >> 4;
    int rblk = blockIdx.x & 15;
    int wid = threadIdx.x >> 5;
    int lane = threadIdx.x & 31;
    int h = wid >> 3;                 // column half 0/1
    int p = wid & 7;                  // pair id / row group

    __shared__ float red[2][8][512];  // 32 KB block-reduce staging
    __shared__ float sx[8][2][2];     // [pair][buf][half] half-dot exchange
    __shared__ float mus[128];

    if (threadIdx.x < 128)
        mus[threadIdx.x] = mu[(n << 11) + rblk * 128 + threadIdx.x] + LOG_EPS;

    int gid = blockIdx.x * 512 + threadIdx.x;     // 0..65535
    float nuv = 0.f;
    if (gid < NB * P) {
        nuv = nu[gid] + LOG_EPS;
        g_wv[gid] = 1.0f;
    }
    grid_sync();

    const int4* Eb = (const int4*)(g_Eh + ((size_t)n << 22)) + h * 128;
    const float4* wvb4 = (const float4*)(g_wv + (n << 11) + h * 1024);
    int i0 = rblk * 128 + p * 16;

    for (int it = 0; it < MAX_ITER; it++) {
        // reload lane's 32 wv values into 16 f32x2 regs (8 LDG.128)
        ull wv2[16];
#pragma unroll
        for (int c = 0; c < 4; c++) {
            float4 A = wvb4[64 * c + 2 * lane];
            float4 B = wvb4[64 * c + 2 * lane + 1];
            wv2[c * 4 + 0] = pk(A.x, A.y);
            wv2[c * 4 + 1] = pk(A.z, A.w);
            wv2[c * 4 + 2] = pk(B.x, B.y);
            wv2[c * 4 + 3] = pk(B.z, B.w);
        }

        ull acc2[16];
        ull z2 = pk(0.f, 0.f);
#pragma unroll
        for (int k = 0; k < 16; k++) acc2[k] = z2;

        // prologue: prefetch row 0's packed E
        int4 raw[4];
        {
            const int4* e4 = Eb + ((size_t)i0 << 8);
#pragma unroll
            for (int c = 0; c < 4; c++) raw[c] = e4[c * 32 + lane];
        }

        for (int r = 0; r < 16; r++) {
            // unpack raw -> ef2 (frees raw for the next prefetch)
            ull ef2[16];
#pragma unroll
            for (int c = 0; c < 4; c++) {
                float2 f0 = h2f((unsigned)raw[c].x);
                float2 f1 = h2f((unsigned)raw[c].y);
                float2 f2 = h2f((unsigned)raw[c].z);
                float2 f3 = h2f((unsigned)raw[c].w);
                ef2[c * 4 + 0] = pk(f0.x, f0.y);
                ef2[c * 4 + 1] = pk(f1.x, f1.y);
                ef2[c * 4 + 2] = pk(f2.x, f2.y);
                ef2[c * 4 + 3] = pk(f3.x, f3.y);
            }

            // prefetch next row NOW — overlaps dot/exchange/div/acc below
            if (r < 15) {
                const int4* nx = Eb + ((size_t)(i0 + r + 1) << 8);
#pragma unroll
                for (int c = 0; c < 4; c++) raw[c] = nx[c * 32 + lane];
            }

            // half-row dot: 16 FFMA2 in 4 chains
            ull sa = z2, sb = z2, sc = z2, sd = z2;
#pragma unroll
            for (int k = 0; k < 16; k += 4) {
                sa = ffma2(ef2[k + 0], wv2[k + 0], sa);
                sb = ffma2(ef2[k + 1], wv2[k + 1], sb);
                sc = ffma2(ef2[k + 2], wv2[k + 2], sc);
                sd = ffma2(ef2[k + 3], wv2[k + 3], sd);
            }
            float xa, xb, xc, xd, ya, yb, yc, yd;
            upk(xa, ya, sa); upk(xb, yb, sb);
            upk(xc, yc, sc); upk(xd, yd, sd);
            float s = ((xa + xb) + (xc + xd)) + ((ya + yb) + (yc + yd));
#pragma unroll
            for (int off = 16; off; off >>= 1)
                s += __shfl_xor_sync(0xffffffffu, s, off);

            // exchange half-dots with partner warp (double-buffered slot)
            int buf = r & 1;
            if (lane == 0) sx[p][buf][h] = s;
            asm volatile("bar.sync %0, 64;" :: "r"(p + 1) : "memory");
            float s_all = s + sx[p][buf][1 - h];

            float wu = mus[p * 16 + r] / s_all;
            if (it == MAX_ITER - 1 && h == 0 && lane == 0)
                g_wu[(n << 11) + i0 + r] = wu;      // only needed at the end
            ull wu2 = pk(wu, wu);

            // column accumulation from the same ef2 registers
#pragma unroll
            for (int k = 0; k < 16; k++)
                acc2[k] = ffma2(ef2[k], wu2, acc2[k]);
        }

        // unpack acc, block-level reduce: 2 chunks of 512 cols per half
        float acc[32];
#pragma unroll
        for (int k = 0; k < 16; k++) upk(acc[2 * k], acc[2 * k + 1], acc2[k]);

        float* bp = g_bpart + ((size_t)(n * 16 + rblk) << 11);
#pragma unroll
        for (int ch = 0; ch < 2; ch++) {
            __syncthreads();
#pragma unroll
            for (int cp = 0; cp < 2; cp++)
#pragma unroll
                for (int h2 = 0; h2 < 8; h2++)
                    red[h][p][cp * 256 + lane * 8 + h2] = acc[(2 * ch + cp) * 8 + h2];
            __syncthreads();
            {
                int t = threadIdx.x;
                float v0 = 0.f, v1 = 0.f;
#pragma unroll
                for (int w = 0; w < 8; w++) {
                    v0 += red[0][w][t];
                    v1 += red[1][w][t];
                }
                bp[ch * 512 + t]        = v0;
                bp[1024 + ch * 512 + t] = v1;
            }
        }

        grid_sync();                               // all block partials visible

        // distributed combine: 1 thread per (n,j)
        if (gid < NB * P) {
            int nn = gid >> 11, j = gid & 2047;
            const float* pp = g_bpart + ((size_t)(nn * 16) << 11) + j;
            float t0 = 0.f, t1 = 0.f, t2 = 0.f, t3 = 0.f;
#pragma unroll
            for (int b = 0; b < 16; b += 4) {
                t0 += pp[(size_t)(b + 0) << 11];
                t1 += pp[(size_t)(b + 1) << 11];
                t2 += pp[(size_t)(b + 2) << 11];
                t3 += pp[(size_t)(b + 3) << 11];
            }
            g_wv[gid] = nuv / ((t0 + t1) + (t2 + t3));
        }

        grid_sync();                               // wv complete for next iter
    }
}

// ---------------------------------------------------------------- epilogue
__global__ void __launch_bounds__(256) final_pi(const float* __restrict__ C,
                                                float* __restrict__ out,
                                                int out_size) {
    int rowg = blockIdx.x;              // 0..16383
    int n = rowg >> 11, i = rowg & 2047;
    size_t base = ((size_t)n << 22) + ((size_t)i << 11);
    float wui = g_wu[(n << 11) + i];

    const int4* e4 = (const int4*)(g_Eh + base);
    const float4* c4 = (const float4*)(C + base);
    const float4* w4 = (const float4*)(g_wv + (n << 11));

    bool wpi = out_size >= 8 + TOT;
    bool wc  = out_size >= 8 + 2 * TOT;
    float4* pio = (float4*)(out + 8) + base / 4;
    float4* cco = (float4*)(out + 8 + (size_t)TOT) + base / 4;

    int t = threadIdx.x;
    int4 r = e4[t];
    float4 cA = c4[2 * t], cB = c4[2 * t + 1];
    float4 wA = w4[2 * t], wB = w4[2 * t + 1];
    float2 f0 = h2f((unsigned)r.x);
    float2 f1 = h2f((unsigned)r.y);
    float2 f2 = h2f((unsigned)r.z);
    float2 f3 = h2f((unsigned)r.w);
    float4 pA, pB;
    pA.x = f0.x * wui * wA.x;  pA.y = f0.y * wui * wA.y;
    pA.z = f1.x * wui * wA.z;  pA.w = f1.y * wui * wA.w;
    pB.x = f2.x * wui * wB.x;  pB.y = f2.y * wui * wB.y;
    pB.z = f3.x * wui * wB.z;  pB.w = f3.y * wui * wB.w;
    if (wpi) { pio[2 * t] = pA; pio[2 * t + 1] = pB; }
    if (wc)  { cco[2 * t] = cA; cco[2 * t + 1] = cB; }
    float cl = 0.f;
    cl = fmaf(pA.x, cA.x, fmaf(pA.y, cA.y, fmaf(pA.z, cA.z, fmaf(pA.w, cA.w, cl))));
    cl = fmaf(pB.x, cB.x, fmaf(pB.y, cB.y, fmaf(pB.z, cB.z, fmaf(pB.w, cB.w, cl))));

    __shared__ float red[256];
    red[t] = cl;
    __syncthreads();
    for (int s2 = 128; s2 > 0; s2 >>= 1) {
        if (t < s2) red[t] += red[t + s2];
        __syncthreads();
    }
    if (t == 0) g_costpart[rowg] = red[0];
}

__global__ void cost_combine(float* __restrict__ out, int out_size) {
    int n = blockIdx.x;
    __shared__ float red[256];
    const float* p = g_costpart + (n << 11);
    float s = 0.f;
    for (int k = threadIdx.x; k < P; k += 256) s += p[k];
    red[threadIdx.x] = s;
    __syncthreads();
    for (int s2 = 128; s2 > 0; s2 >>= 1) {
        if (threadIdx.x < s2) red[threadIdx.x] += red[threadIdx.x + s2];
        __syncthreads();
    }
    if (threadIdx.x == 0 && out_size > n) out[n] = red[0];
}

// ------------------------------------------------------------------ launch
extern "C" void kernel_launch(void* const* d_in, const int* in_sizes, int n_in,
                              void* d_out, int out_size) {
    const float* C  = (const float*)d_in[0];
    const float* mu = (const float*)d_in[1];
    const float* nu = (const float*)d_in[2];
    float* out = (float*)d_out;

    precompute_E<<<4096, 256>>>(C);
    sinkhorn_persist<<<NBLK, 512>>>(mu, nu);
    final_pi<<<16384, 256>>>(C, out, out_size);
    cost_combine<<<8, 256>>>(out, out_size);
}

// round 13
// speedup vs baseline: 1.1312x; 1.1312x over previous
#include <cuda_runtime.h>
#include <cuda_fp16.h>
#include <math.h>

// Sinkhorn on GB300 — persistent kernel, per-batch barriers, local combine.
//   Eh = exp(-C/eps) in fp16 (64 MB, L2-resident).
//   8 batches x 16 blocks. ONE 16-block barrier per iteration; every block
//   then locally combines the 16 column-partials (redundant but sync-free)
//   into smem wvs and reloads its wv registers. bpart double-buffered.
//   g_wu/g_wv written only on the last iteration.

#define P 2048
#define NB 8
#define INV_EPS 10.0f
#define LOG_EPS 1e-8f
#define MAX_ITER 50
#define TOT 33554432           // NB * P * P
#define NBLK 128

typedef unsigned long long ull;

__device__ __half g_Eh[TOT];
__device__ float g_wu[NB * P];
__device__ float g_wv[NB * P];
__device__ float g_bpart[2][NB * 16 * P];   // double-buffered block partials
__device__ float g_costpart[NB * P];

__device__ unsigned g_arr[NB * 32];          // per-batch arrive ctr (128B stride)
__device__ volatile unsigned g_genB[NB * 32];// per-batch generation

__device__ __forceinline__ float2 h2f(unsigned int u) {
    __half2 h = *reinterpret_cast<__half2*>(&u);
    return __half22float2(h);
}
__device__ __forceinline__ ull pk(float a, float b) {
    ull r; asm("mov.b64 %0, {%1, %2};" : "=l"(r) : "f"(a), "f"(b)); return r;
}
__device__ __forceinline__ void upk(float& a, float& b, ull r) {
    asm("mov.b64 {%0, %1}, %2;" : "=f"(a), "=f"(b) : "l"(r));
}
__device__ __forceinline__ ull ffma2(ull a, ull b, ull c) {
    ull d; asm("fma.rn.f32x2 %0, %1, %2, %3;" : "=l"(d) : "l"(a), "l"(b), "l"(c));
    return d;
}

// per-batch sense-reversing barrier: 16 blocks of batch n.
__device__ __forceinline__ void batch_sync(int n) {
    __syncthreads();
    if (threadIdx.x == 0) {
        unsigned g = g_genB[n * 32];
        __threadfence();                       // release: bpart writes visible
        if (atomicAdd(&g_arr[n * 32], 1u) == 15u) {
            g_arr[n * 32] = 0;
            __threadfence();
            g_genB[n * 32] = g + 1;
        } else {
            while (g_genB[n * 32] == g) __nanosleep(32);
        }
        __threadfence();                       // acquire
    }
    __syncthreads();
}

// ---------------------------------------------------------------- precompute
__global__ void precompute_E(const float* __restrict__ C) {
    size_t stride = (size_t)gridDim.x * blockDim.x;
    const float4* c4 = (const float4*)C;
    int4* e4 = (int4*)g_Eh;
    for (size_t k = (size_t)blockIdx.x * blockDim.x + threadIdx.x;
         k < (size_t)TOT / 8; k += stride) {
        float4 a = c4[2 * k], b = c4[2 * k + 1];
        __half2 h0 = __floats2half2_rn(expf(-a.x * INV_EPS), expf(-a.y * INV_EPS));
        __half2 h1 = __floats2half2_rn(expf(-a.z * INV_EPS), expf(-a.w * INV_EPS));
        __half2 h2 = __floats2half2_rn(expf(-b.x * INV_EPS), expf(-b.y * INV_EPS));
        __half2 h3 = __floats2half2_rn(expf(-b.z * INV_EPS), expf(-b.w * INV_EPS));
        int4 o;
        o.x = *reinterpret_cast<int*>(&h0);
        o.y = *reinterpret_cast<int*>(&h1);
        o.z = *reinterpret_cast<int*>(&h2);
        o.w = *reinterpret_cast<int*>(&h3);
        e4[k] = o;
    }
}

// --------------------------------------------------------- persistent kernel
// block = (n, rblk): rows [rblk*128, +128). 16 warps: h = wid>>3 (col half),
// p = wid&7 (rows p*16..p*16+15). lane owns cols h*1024+256c+8*lane+h2.
__global__ void __launch_bounds__(512, 1)
sinkhorn_persist(const float* __restrict__ mu, const float* __restrict__ nu) {
    int n = blockIdx.x >> 4;
    int rblk = blockIdx.x & 15;
    int wid = threadIdx.x >> 5;
    int lane = threadIdx.x & 31;
    int h = wid >> 3;                 // column half 0/1
    int p = wid & 7;                  // pair id / row group

    __shared__ float red[2][8][512];            // 32 KB block-reduce staging
    __shared__ float sx[8][2][2];               // half-dot exchange
    __shared__ float mus[128];
    __shared__ __align__(16) float nus[2048];   // nu + LOG_EPS for this batch
    __shared__ __align__(16) float wvs[2048];   // combined wv, per iteration

    if (threadIdx.x < 128)
        mus[threadIdx.x] = mu[(n << 11) + rblk * 128 + threadIdx.x] + LOG_EPS;
#pragma unroll
    for (int q = 0; q < 4; q++) {
        int j = threadIdx.x + q * 512;
        nus[j] = nu[(n << 11) + j] + LOG_EPS;
    }
    __syncthreads();

    const int4* Eb = (const int4*)(g_Eh + ((size_t)n << 22)) + h * 128;
    int i0 = rblk * 128 + p * 16;

    // wv = 1 initially (register-resident; no global init needed)
    ull wv2[16];
    ull one2 = pk(1.f, 1.f);
#pragma unroll
    for (int k = 0; k < 16; k++) wv2[k] = one2;

    for (int it = 0; it < MAX_ITER; it++) {
        int buf = it & 1;

        ull acc2[16];
        ull z2 = pk(0.f, 0.f);
#pragma unroll
        for (int k = 0; k < 16; k++) acc2[k] = z2;

        // prologue: prefetch row 0's packed E
        int4 raw[4];
        {
            const int4* e4 = Eb + ((size_t)i0 << 8);
#pragma unroll
            for (int c = 0; c < 4; c++) raw[c] = e4[c * 32 + lane];
        }

        for (int r = 0; r < 16; r++) {
            ull ef2[16];
#pragma unroll
            for (int c = 0; c < 4; c++) {
                float2 f0 = h2f((unsigned)raw[c].x);
                float2 f1 = h2f((unsigned)raw[c].y);
                float2 f2 = h2f((unsigned)raw[c].z);
                float2 f3 = h2f((unsigned)raw[c].w);
                ef2[c * 4 + 0] = pk(f0.x, f0.y);
                ef2[c * 4 + 1] = pk(f1.x, f1.y);
                ef2[c * 4 + 2] = pk(f2.x, f2.y);
                ef2[c * 4 + 3] = pk(f3.x, f3.y);
            }

            if (r < 15) {          // prefetch next row, overlaps chain below
                const int4* nx = Eb + ((size_t)(i0 + r + 1) << 8);
#pragma unroll
                for (int c = 0; c < 4; c++) raw[c] = nx[c * 32 + lane];
            }

            ull sa = z2, sb = z2, sc = z2, sd = z2;
#pragma unroll
            for (int k = 0; k < 16; k += 4) {
                sa = ffma2(ef2[k + 0], wv2[k + 0], sa);
                sb = ffma2(ef2[k + 1], wv2[k + 1], sb);
                sc = ffma2(ef2[k + 2], wv2[k + 2], sc);
                sd = ffma2(ef2[k + 3], wv2[k + 3], sd);
            }
            float xa, xb, xc, xd, ya, yb, yc, yd;
            upk(xa, ya, sa); upk(xb, yb, sb);
            upk(xc, yc, sc); upk(xd, yd, sd);
            float s = ((xa + xb) + (xc + xd)) + ((ya + yb) + (yc + yd));
#pragma unroll
            for (int off = 16; off; off >>= 1)
                s += __shfl_xor_sync(0xffffffffu, s, off);

            int bu = r & 1;
            if (lane == 0) sx[p][bu][h] = s;
            asm volatile("bar.sync %0, 64;" :: "r"(p + 1) : "memory");
            float s_all = s + sx[p][bu][1 - h];

            float wu = mus[p * 16 + r] / s_all;
            if (it == MAX_ITER - 1 && h == 0 && lane == 0)
                g_wu[(n << 11) + i0 + r] = wu;
            ull wu2 = pk(wu, wu);

#pragma unroll
            for (int k = 0; k < 16; k++)
                acc2[k] = ffma2(ef2[k], wu2, acc2[k]);
        }

        // unpack acc, block-level reduce: 2 chunks of 512 cols per half
        float acc[32];
#pragma unroll
        for (int k = 0; k < 16; k++) upk(acc[2 * k], acc[2 * k + 1], acc2[k]);

        float* bp = g_bpart[buf] + ((size_t)(n * 16 + rblk) << 11);
#pragma unroll
        for (int ch = 0; ch < 2; ch++) {
            __syncthreads();
#pragma unroll
            for (int cp = 0; cp < 2; cp++)
#pragma unroll
                for (int h2 = 0; h2 < 8; h2++)
                    red[h][p][cp * 256 + lane * 8 + h2] = acc[(2 * ch + cp) * 8 + h2];
            __syncthreads();
            {
                int t = threadIdx.x;
                float v0 = 0.f, v1 = 0.f;
#pragma unroll
                for (int w = 0; w < 8; w++) {
                    v0 += red[0][w][t];
                    v1 += red[1][w][t];
                }
                bp[ch * 512 + t]        = v0;
                bp[1024 + ch * 512 + t] = v1;
            }
        }

        batch_sync(n);                 // the ONLY global sync this iteration

        // local combine: every block redundantly computes all 2048 wv
        const float* bpb = g_bpart[buf] + ((size_t)(n * 16) << 11);
#pragma unroll
        for (int q = 0; q < 4; q++) {
            int j = threadIdx.x + q * 512;
            float t0 = 0.f, t1 = 0.f, t2 = 0.f, t3 = 0.f;
#pragma unroll
            for (int b = 0; b < 16; b += 4) {
                t0 += bpb[((size_t)(b + 0) << 11) + j];
                t1 += bpb[((size_t)(b + 1) << 11) + j];
                t2 += bpb[((size_t)(b + 2) << 11) + j];
                t3 += bpb[((size_t)(b + 3) << 11) + j];
            }
            wvs[j] = nus[j] / ((t0 + t1) + (t2 + t3));
        }
        __syncthreads();

        // reload lane's wv registers from smem
#pragma unroll
        for (int c = 0; c < 4; c++) {
            const float* wp = &wvs[h * 1024 + 256 * c + 8 * lane];
            float4 A = *(const float4*)(wp);
            float4 B = *(const float4*)(wp + 4);
            wv2[c * 4 + 0] = pk(A.x, A.y);
            wv2[c * 4 + 1] = pk(A.z, A.w);
            wv2[c * 4 + 2] = pk(B.x, B.y);
            wv2[c * 4 + 3] = pk(B.z, B.w);
        }

        if (it == MAX_ITER - 1 && rblk == 0) {     // publish final wv
#pragma unroll
            for (int q = 0; q < 4; q++) {
                int j = threadIdx.x + q * 512;
                g_wv[(n << 11) + j] = wvs[j];
            }
        }
    }
}

// ---------------------------------------------------------------- epilogue
__global__ void __launch_bounds__(256) final_pi(const float* __restrict__ C,
                                                float* __restrict__ out,
                                                int out_size) {
    int rowg = blockIdx.x;              // 0..16383
    int n = rowg >> 11, i = rowg & 2047;
    size_t base = ((size_t)n << 22) + ((size_t)i << 11);
    float wui = g_wu[(n << 11) + i];

    const int4* e4 = (const int4*)(g_Eh + base);
    const float4* c4 = (const float4*)(C + base);
    const float4* w4 = (const float4*)(g_wv + (n << 11));

    bool wpi = out_size >= 8 + TOT;
    bool wc  = out_size >= 8 + 2 * TOT;
    float4* pio = (float4*)(out + 8) + base / 4;
    float4* cco = (float4*)(out + 8 + (size_t)TOT) + base / 4;

    int t = threadIdx.x;
    int4 r = e4[t];
    float4 cA = c4[2 * t], cB = c4[2 * t + 1];
    float4 wA = w4[2 * t], wB = w4[2 * t + 1];
    float2 f0 = h2f((unsigned)r.x);
    float2 f1 = h2f((unsigned)r.y);
    float2 f2 = h2f((unsigned)r.z);
    float2 f3 = h2f((unsigned)r.w);
    float4 pA, pB;
    pA.x = f0.x * wui * wA.x;  pA.y = f0.y * wui * wA.y;
    pA.z = f1.x * wui * wA.z;  pA.w = f1.y * wui * wA.w;
    pB.x = f2.x * wui * wB.x;  pB.y = f2.y * wui * wB.y;
    pB.z = f3.x * wui * wB.z;  pB.w = f3.y * wui * wB.w;
    if (wpi) { pio[2 * t] = pA; pio[2 * t + 1] = pB; }
    if (wc)  { cco[2 * t] = cA; cco[2 * t + 1] = cB; }
    float cl = 0.f;
    cl = fmaf(pA.x, cA.x, fmaf(pA.y, cA.y, fmaf(pA.z, cA.z, fmaf(pA.w, cA.w, cl))));
    cl = fmaf(pB.x, cB.x, fmaf(pB.y, cB.y, fmaf(pB.z, cB.z, fmaf(pB.w, cB.w, cl))));

    __shared__ float red[256];
    red[t] = cl;
    __syncthreads();
    for (int s2 = 128; s2 > 0; s2 >>= 1) {
        if (t < s2) red[t] += red[t + s2];
        __syncthreads();
    }
    if (t == 0) g_costpart[rowg] = red[0];
}

__global__ void cost_combine(float* __restrict__ out, int out_size) {
    int n = blockIdx.x;
    __shared__ float red[256];
    const float* p = g_costpart + (n << 11);
    float s = 0.f;
    for (int k = threadIdx.x; k < P; k += 256) s += p[k];
    red[threadIdx.x] = s;
    __syncthreads();
    for (int s2 = 128; s2 > 0; s2 >>= 1) {
        if (threadIdx.x < s2) red[threadIdx.x] += red[threadIdx.x + s2];
        __syncthreads();
    }
    if (threadIdx.x == 0 && out_size > n) out[n] = red[0];
}

// ------------------------------------------------------------------ launch
extern "C" void kernel_launch(void* const* d_in, const int* in_sizes, int n_in,
                              void* d_out, int out_size) {
    const float* C  = (const float*)d_in[0];
    const float* mu = (const float*)d_in[1];
    const float* nu = (const float*)d_in[2];
    float* out = (float*)d_out;

    precompute_E<<<4096, 256>>>(C);
    sinkhorn_persist<<<NBLK, 512>>>(mu, nu);
    final_pi<<<16384, 256>>>(C, out, out_size);
    cost_combine<<<8, 256>>>(out, out_size);
}